// round 7
// baseline (speedup 1.0000x reference)
#include <cuda_runtime.h>
#include <cuda_bf16.h>
#include <cuda_fp16.h>
#include <cstdint>

// ---------------- problem constants ----------------
#define S_LEN   256
#define HID     2048
#define NK      4
#define NV      32
#define DK      128
#define DV      128
#define KEY_DIM 512          // NK*DK
#define VAL_DIM 4096         // NV*DV
#define CONV_DIM 5120        // 2*KEY_DIM + VAL_DIM
#define QKVZ_DIM 9216        // 2*KEY_DIM + 2*VAL_DIM
#define Q_SCALE 0.08838834764831845f   // DK^-0.5
#define EPS 1e-6f

typedef unsigned long long u64;
typedef unsigned int u32;

// ---------------- scratch (static device memory, allowed) ----------------
__device__ float g_qkvz[S_LEN * QKVZ_DIM];      // 9.4 MB
__device__ float g_ba  [S_LEN * 64];
__device__ float g_conv[S_LEN * CONV_DIM];      // 5.2 MB
__device__ float g_Vbt [VAL_DIM * S_LEN];       // [n=h*128+d][t]  (v*beta transposed)
__device__ float g_S   [NK * S_LEN * S_LEN];    // [g][s][t]  4 group score mats (1 MB)
__device__ float g_attn[S_LEN * VAL_DIM];       // [s][h*128+d]
__device__ float g_part[4 * S_LEN * HID];       // out_proj K-split partials

// ================= low-level helpers =================
__device__ __forceinline__ u32 smem_u32(const void* p) {
    u32 a;
    asm("{ .reg .u64 t; cvta.to.shared.u64 t, %1; cvt.u32.u64 %0, t; }" : "=r"(a) : "l"(p));
    return a;
}
__device__ __forceinline__ void sts128(u32 addr, uint4 v) {
    asm volatile("st.shared.v4.b32 [%0], {%1,%2,%3,%4};"
                 :: "r"(addr), "r"(v.x), "r"(v.y), "r"(v.z), "r"(v.w) : "memory");
}
__device__ __forceinline__ void ldsm4(u32* r, u32 addr) {
    asm volatile("ldmatrix.sync.aligned.m8n8.x4.shared.b16 {%0,%1,%2,%3}, [%4];"
                 : "=r"(r[0]), "=r"(r[1]), "=r"(r[2]), "=r"(r[3]) : "r"(addr));
}
__device__ __forceinline__ void ldsm2(u32* r, u32 addr) {
    asm volatile("ldmatrix.sync.aligned.m8n8.x2.shared.b16 {%0,%1}, [%2];"
                 : "=r"(r[0]), "=r"(r[1]) : "r"(addr));
}
__device__ __forceinline__ void mma_f16(float* c, const u32* a, const u32* b) {
    asm volatile("mma.sync.aligned.m16n8k16.row.col.f32.f16.f16.f32 "
                 "{%0,%1,%2,%3}, {%4,%5,%6,%7}, {%8,%9}, {%0,%1,%2,%3};"
                 : "+f"(c[0]), "+f"(c[1]), "+f"(c[2]), "+f"(c[3])
                 : "r"(a[0]), "r"(a[1]), "r"(a[2]), "r"(a[3]), "r"(b[0]), "r"(b[1]));
}

__device__ __forceinline__ u32 packh(__half a, __half b) {
    __half2 h = __halves2half2(a, b);
    return *(u32*)&h;
}
// fp32 -> fp16 hi + fp16 lo (2-way split), 2 values packed per u32
__device__ __forceinline__ void cvt2s(float a, float b, u32& hi, u32& lo) {
    __half ha = __float2half_rn(a), hb = __float2half_rn(b);
    float ra = a - __half2float(ha), rb = b - __half2float(hb);
    hi = packh(ha, hb);
    lo = packh(__float2half_rn(ra), __float2half_rn(rb));
}
__device__ __forceinline__ void cvt8s(float4 p0, float4 p1, uint4& hi, uint4& lo) {
    cvt2s(p0.x, p0.y, hi.x, lo.x);
    cvt2s(p0.z, p0.w, hi.y, lo.y);
    cvt2s(p1.x, p1.y, hi.z, lo.z);
    cvt2s(p1.z, p1.w, hi.w, lo.w);
}
// fp32 -> fp16 single (for B operand)
__device__ __forceinline__ uint4 cvt8h(float4 p0, float4 p1) {
    uint4 r;
    __half2 h0 = __floats2half2_rn(p0.x, p0.y);
    __half2 h1 = __floats2half2_rn(p0.z, p0.w);
    __half2 h2 = __floats2half2_rn(p1.x, p1.y);
    __half2 h3 = __floats2half2_rn(p1.z, p1.w);
    r.x = *(u32*)&h0; r.y = *(u32*)&h1; r.z = *(u32*)&h2; r.w = *(u32*)&h3;
    return r;
}

// ================= mma.sync fp16 2-pass GEMM: C = A * B^T =================
// A [M,K] fp32 row-major (lda), B [N,K] fp32 row-major (ldb), C fp32 row-major.
// Tile 128x128, K-chunk 32, double-buffered SMEM: Ahi/Alo (fp16 split) + B (fp16).
// C = Ahi*B + Alo*B   (rel err ~2^-12 per GEMM).
// Single-sync pipelined mainloop: mma(it) -> store(it+1) -> ldg(it+2) -> sync.
// SMEM stage (24KB): Ahi @0, Alo @8192, B @16384. 2 stages = 48KB.
#define MMA_SMEM_TOTAL 49152

__global__ void __launch_bounds__(256)
gemm_mma(const float* __restrict__ A, int lda, int zA,
         const float* __restrict__ B, int ldb, int zB,
         float* __restrict__ C, int ldc, int zC,
         int Ktot, int ksplit, int causal, float scale)
{
    extern __shared__ char smem[];
    const u32 sb = smem_u32(smem);
    const int tid = threadIdx.x;
    const int wid = tid >> 5, lane = tid & 31;
    const int bm = blockIdx.x * 128, bn = blockIdx.y * 128;
    const int z = blockIdx.z;

    int kLen = Ktot, k0 = 0;
    if (ksplit > 1) {
        kLen = Ktot / ksplit;
        k0 = z * kLen;
        C += (size_t)z * zC;
    } else {
        A += (size_t)z * zA;
        B += (size_t)z * zB;
        C += (size_t)z * zC;
    }
    const int niter = kLen / 32;

    // ---- global load mapping: thread -> (row 0..127, 16-float half) ----
    const int grow = tid >> 1;
    const int ghalf = tid & 1;
    const float* Ap = A + (size_t)(bm + grow) * lda + k0 + ghalf * 16;
    const float* Bp = B + (size_t)(bn + grow) * ldb + k0 + ghalf * 16;
    const int ssw = (grow >> 1) & 3;
    const u32 st0 = (u32)(grow * 64 + (((ghalf * 2 + 0) ^ ssw) * 16));
    const u32 st1 = (u32)(grow * 64 + (((ghalf * 2 + 1) ^ ssw) * 16));

    // ---- warp tile: 2(m) x 4(n), each 64x32 ----
    const int wm = wid & 1, wn = wid >> 1;
    const int arow = wm * 64 + (lane & 15);
    const u32 arow_b = (u32)(arow * 64);
    const int aswz = (arow >> 1) & 3;
    const int ahi = lane >> 4;
    const int brow = wn * 32 + (lane & 7);
    const u32 brow_b = (u32)(brow * 64);
    const int bswz = (brow >> 1) & 3;
    const int bhi = (lane >> 3) & 1;

    float acc[4][4][4];
#pragma unroll
    for (int i = 0; i < 4; i++)
#pragma unroll
        for (int j = 0; j < 4; j++)
#pragma unroll
            for (int q = 0; q < 4; q++) acc[i][j][q] = 0.f;

    float4 ra[4], rb[4];
    // ---- prologue: load chunk 0, store to stage 0, prefetch chunk 1 ----
#pragma unroll
    for (int j = 0; j < 4; j++) {
        ra[j] = *(const float4*)(Ap + j * 4);
        rb[j] = *(const float4*)(Bp + j * 4);
    }
    {
        uint4 hi, lo;
        cvt8s(ra[0], ra[1], hi, lo);
        sts128(sb + st0, hi);
        sts128(sb + 8192 + st0, lo);
        cvt8s(ra[2], ra[3], hi, lo);
        sts128(sb + st1, hi);
        sts128(sb + 8192 + st1, lo);
        sts128(sb + 16384 + st0, cvt8h(rb[0], rb[1]));
        sts128(sb + 16384 + st1, cvt8h(rb[2], rb[3]));
    }
    if (niter > 1) {
#pragma unroll
        for (int j = 0; j < 4; j++) {
            ra[j] = *(const float4*)(Ap + 32 + j * 4);
            rb[j] = *(const float4*)(Bp + 32 + j * 4);
        }
    }
    __syncthreads();

    for (int it = 0; it < niter; it++) {
        const u32 stg = sb + (u32)((it & 1) * 24576);
        // ---- MMA on stage(it) ----
#pragma unroll
        for (int ks = 0; ks < 2; ks++) {
            u32 ah[4][4], al[4][4], bh[4][2];
            const u32 ac = (u32)((((ks * 2 + ahi) ^ aswz)) * 16);
            const u32 abase = stg + arow_b + ac;
#pragma unroll
            for (int mi = 0; mi < 4; mi++) ldsm4(ah[mi], abase + mi * 1024);
#pragma unroll
            for (int mi = 0; mi < 4; mi++) ldsm4(al[mi], abase + 8192 + mi * 1024);
            const u32 bc = (u32)((((ks * 2 + bhi) ^ bswz)) * 16);
            const u32 bbase = stg + 16384 + brow_b + bc;
#pragma unroll
            for (int nj = 0; nj < 4; nj++) ldsm2(bh[nj], bbase + nj * 512);
#pragma unroll
            for (int mi = 0; mi < 4; mi++)
#pragma unroll
                for (int nj = 0; nj < 4; nj++) {
                    mma_f16(acc[mi][nj], ah[mi], bh[nj]);
                    mma_f16(acc[mi][nj], al[mi], bh[nj]);
                }
        }
        // ---- store chunk it+1 to other stage; prefetch chunk it+2 ----
        if (it + 1 < niter) {
            const u32 nstg = sb + (u32)(((it + 1) & 1) * 24576);
            uint4 hi, lo;
            cvt8s(ra[0], ra[1], hi, lo);
            sts128(nstg + st0, hi);
            sts128(nstg + 8192 + st0, lo);
            cvt8s(ra[2], ra[3], hi, lo);
            sts128(nstg + st1, hi);
            sts128(nstg + 8192 + st1, lo);
            sts128(nstg + 16384 + st0, cvt8h(rb[0], rb[1]));
            sts128(nstg + 16384 + st1, cvt8h(rb[2], rb[3]));
            if (it + 2 < niter) {
                const float* a = Ap + (it + 2) * 32;
                const float* b = Bp + (it + 2) * 32;
#pragma unroll
                for (int j = 0; j < 4; j++) {
                    ra[j] = *(const float4*)(a + j * 4);
                    rb[j] = *(const float4*)(b + j * 4);
                }
            }
        }
        __syncthreads();
    }

    // ---- epilogue (scale + optional causal mask: zero where col > row) ----
    const int crow0 = bm + wm * 64 + (lane >> 2);
    const int ccol0 = bn + wn * 32 + (lane & 3) * 2;
#pragma unroll
    for (int mi = 0; mi < 4; mi++)
#pragma unroll
        for (int nj = 0; nj < 4; nj++) {
            const int r = crow0 + mi * 16;
            const int c = ccol0 + nj * 8;
            float v0 = acc[mi][nj][0] * scale;
            float v1 = acc[mi][nj][1] * scale;
            float v2 = acc[mi][nj][2] * scale;
            float v3 = acc[mi][nj][3] * scale;
            if (causal) {
                if (c     > r)     v0 = 0.f;
                if (c + 1 > r)     v1 = 0.f;
                if (c     > r + 8) v2 = 0.f;
                if (c + 1 > r + 8) v3 = 0.f;
            }
            *(float2*)(C + (size_t)r * ldc + c) = make_float2(v0, v1);
            *(float2*)(C + (size_t)(r + 8) * ldc + c) = make_float2(v2, v3);
        }
}

// ---------------- ba = hs @ w_ba^T  (N=64, tiny; overlapped with qkvz) -------
__global__ void ba_gemm(const float* __restrict__ hs, const float* __restrict__ w,
                        float* __restrict__ ba)
{
    const int s = blockIdx.x;
    const int t = threadIdx.x;
    const int n = t & 63, kc = t >> 6;
    const float4* a = (const float4*)(hs + (size_t)s * HID + kc * 512);
    const float4* b = (const float4*)(w + (size_t)n * HID + kc * 512);
    float acc = 0.f;
#pragma unroll 8
    for (int i = 0; i < 128; i++) {
        float4 x = a[i], y = b[i];
        acc += x.x * y.x + x.y * y.y + x.z * y.z + x.w * y.w;
    }
    __shared__ float red[256];
    red[t] = acc;
    __syncthreads();
    if (t < 64)
        ba[s * 64 + n] = red[n] + red[n + 64] + red[n + 128] + red[n + 192];
}

// ---------------- causal depthwise conv (K=4) + SiLU, sliding window --------
__global__ void conv_silu(const float* __restrict__ qkvz, const float* __restrict__ cw,
                          float* __restrict__ out)
{
    const int c = blockIdx.x * 256 + threadIdx.x;   // 0..5119
    const int s0 = blockIdx.y * 64;
    const float4 w = ((const float4*)cw)[c];
    float x0 = 0.f, x1 = 0.f, x2 = 0.f;
    if (s0 >= 1) x2 = qkvz[(size_t)(s0 - 1) * QKVZ_DIM + c];
    if (s0 >= 2) x1 = qkvz[(size_t)(s0 - 2) * QKVZ_DIM + c];
    if (s0 >= 3) x0 = qkvz[(size_t)(s0 - 3) * QKVZ_DIM + c];
#pragma unroll 4
    for (int i = 0; i < 64; i++) {
        const int s = s0 + i;
        float x3 = qkvz[(size_t)s * QKVZ_DIM + c];
        float acc = w.x * x0 + w.y * x1 + w.z * x2 + w.w * x3;
        out[(size_t)s * CONV_DIM + c] = acc / (1.f + expf(-acc));
        x0 = x1; x1 = x2; x2 = x3;
    }
}

// ---------------- Vbt = (v * beta)^T : [n][t], 32n x 128t per block ----------
__global__ void prep_vbt(const float* __restrict__ conv, const float* __restrict__ ba,
                         const float* __restrict__ dt_bias, float* __restrict__ Vbt)
{
    __shared__ float tile[4][32][33];
    const int n0 = blockIdx.x * 32, t0 = blockIdx.y * 128;
    const int tx = threadIdx.x, ty = threadIdx.y;   // 32 x 8
    const int h = (n0 + tx) >> 7;
#pragma unroll
    for (int j = 0; j < 4; j++)
#pragma unroll
        for (int jj = 0; jj < 4; jj++) {
            const int tt = j * 32 + jj * 8 + ty;
            const int t = t0 + tt;
            float b = ba[t * 64 + h] + dt_bias[h];
            float beta = 1.f / (1.f + expf(-b));
            tile[j][jj * 8 + ty][tx] = conv[(size_t)t * CONV_DIM + 2 * KEY_DIM + n0 + tx] * beta;
        }
    __syncthreads();
#pragma unroll
    for (int j = 0; j < 4; j++)
#pragma unroll
        for (int jj = 0; jj < 4; jj++) {
            const int n = n0 + jj * 8 + ty;
            const int t = t0 + j * 32 + tx;
            Vbt[(size_t)n * S_LEN + t] = tile[j][tx][jj * 8 + ty];
        }
}

// ---------------- gated RMSNorm (in-place on g_attn) ----------------
__global__ void rmsnorm_gate(float* __restrict__ attn, const float* __restrict__ qkvz,
                             const float* __restrict__ norm_w)
{
    const int s = blockIdx.x >> 5, h = blockIdx.x & 31, d = threadIdx.x;
    const int oi = (s << 12) + (h << 7) + d;
    float o = attn[oi];
    float sq = o * o;
#pragma unroll
    for (int off = 16; off; off >>= 1) sq += __shfl_xor_sync(0xffffffffu, sq, off);
    __shared__ float wsum[4];
    if ((d & 31) == 0) wsum[d >> 5] = sq;
    __syncthreads();
    float var = (wsum[0] + wsum[1] + wsum[2] + wsum[3]) * (1.f / 128.f);
    float r = rsqrtf(var + EPS);
    float zv = qkvz[(size_t)s * QKVZ_DIM + CONV_DIM + (h << 7) + d];
    float g = zv / (1.f + expf(-zv));
    attn[oi] = o * r * norm_w[d] * g;
}

// ---------------- K-split partial reduction ----------------
__global__ void reduce4(const float* __restrict__ p, float* __restrict__ out)
{
    const int i = blockIdx.x * 256 + threadIdx.x;
    out[i] = p[i] + p[i + S_LEN * HID] + p[i + 2 * S_LEN * HID] + p[i + 3 * S_LEN * HID];
}

// ---------------- launch ----------------
extern "C" void kernel_launch(void* const* d_in, const int* in_sizes, int n_in,
                              void* d_out, int out_size)
{
    const float* hs      = (const float*)d_in[0];  // [256,2048]
    const float* w_qkvz  = (const float*)d_in[1];  // [9216,2048]
    const float* w_ba    = (const float*)d_in[2];  // [64,2048]
    const float* w_out   = (const float*)d_in[3];  // [2048,4096]
    const float* conv_w  = (const float*)d_in[4];  // [5120,1,4]
    const float* dt_bias = (const float*)d_in[5];  // [32]
    const float* norm_w  = (const float*)d_in[7];  // [128]
    float* out = (float*)d_out;

    float *qkvz, *ba, *conv, *Vbt, *Sb, *attn, *part;
    cudaGetSymbolAddress((void**)&qkvz, g_qkvz);
    cudaGetSymbolAddress((void**)&ba,   g_ba);
    cudaGetSymbolAddress((void**)&conv, g_conv);
    cudaGetSymbolAddress((void**)&Vbt,  g_Vbt);
    cudaGetSymbolAddress((void**)&Sb,   g_S);
    cudaGetSymbolAddress((void**)&attn, g_attn);
    cudaGetSymbolAddress((void**)&part, g_part);

    static cudaStream_t s1 = nullptr;
    static cudaEvent_t ev_start = nullptr, ev_conv = nullptr, ev_side = nullptr;
    static int init_done = 0;
    if (!init_done) {
        cudaFuncSetAttribute(gemm_mma, cudaFuncAttributeMaxDynamicSharedMemorySize,
                             MMA_SMEM_TOTAL);
        cudaStreamCreateWithFlags(&s1, cudaStreamNonBlocking);
        cudaEventCreateWithFlags(&ev_start, cudaEventDisableTiming);
        cudaEventCreateWithFlags(&ev_conv, cudaEventDisableTiming);
        cudaEventCreateWithFlags(&ev_side, cudaEventDisableTiming);
        init_done = 1;
    }

    // fork: side stream computes ba concurrently with the big qkvz GEMM
    cudaEventRecord(ev_start, 0);
    cudaStreamWaitEvent(s1, ev_start, 0);
    ba_gemm<<<256, 256, 0, s1>>>(hs, w_ba, ba);

    // 1) qkvz = hs @ w_qkvz^T : [256,9216]
    gemm_mma<<<dim3(2, 72, 1), 256, MMA_SMEM_TOTAL>>>(
        hs, HID, 0, w_qkvz, HID, 0, qkvz, QKVZ_DIM, 0, HID, 1, 0, 1.f);
    // 3) causal depthwise conv + silu (first 5120 cols of qkvz)
    conv_silu<<<dim3(20, 4), 256>>>(qkvz, conv_w, conv);
    cudaEventRecord(ev_conv, 0);

    // side stream: Vbt transpose (needs ba [already on s1] + conv)
    cudaStreamWaitEvent(s1, ev_conv, 0);
    prep_vbt<<<dim3(VAL_DIM / 32, S_LEN / 128), dim3(32, 8), 0, s1>>>(conv, ba, dt_bias, Vbt);
    cudaEventRecord(ev_side, s1);

    // 5) S_g = Q_SCALE * tril(q_g k_g^T) : 4 groups x [256,256] (concurrent w/ prep_vbt)
    gemm_mma<<<dim3(2, 2, NK), 256, MMA_SMEM_TOTAL>>>(
        conv, CONV_DIM, DK, conv + KEY_DIM, CONV_DIM, DK,
        Sb, S_LEN, S_LEN * S_LEN, DK, 1, 1, Q_SCALE);

    // join: O GEMM needs S (main) + Vbt (side)
    cudaStreamWaitEvent(0, ev_side, 0);
    // 6) O = S_g @ Vbt_g^T : 4 groups x [256, 1024] -> attn [s][h*128+d]
    gemm_mma<<<dim3(2, 8, NK), 256, MMA_SMEM_TOTAL>>>(
        Sb, S_LEN, S_LEN * S_LEN, Vbt, S_LEN, 1024 * S_LEN,
        attn, VAL_DIM, 1024, S_LEN, 1, 0, 1.f);
    // 7) gated RMSNorm in place
    rmsnorm_gate<<<S_LEN * NV, 128>>>(attn, qkvz, norm_w);
    // 8) out_proj (K-split 4) -> partials
    gemm_mma<<<dim3(2, 16, 4), 256, MMA_SMEM_TOTAL>>>(
        attn, VAL_DIM, 0, w_out, VAL_DIM, 0, part, HID, S_LEN * HID,
        VAL_DIM, 4, 0, 1.f);
    // 9) reduce partials -> d_out
    reduce4<<<S_LEN * HID / 256, 256>>>(part, out);
}

// round 9
// speedup vs baseline: 1.2074x; 1.2074x over previous
#include <cuda_runtime.h>
#include <cuda_bf16.h>
#include <cuda_fp16.h>
#include <cstdint>

// ---------------- problem constants ----------------
#define S_LEN   256
#define HID     2048
#define NK      4
#define NV      32
#define DK      128
#define DV      128
#define KEY_DIM 512          // NK*DK
#define VAL_DIM 4096         // NV*DV
#define CONV_DIM 5120        // 2*KEY_DIM + VAL_DIM
#define QKVZ_DIM 9216        // 2*KEY_DIM + 2*VAL_DIM
#define Q_SCALE 0.08838834764831845f   // DK^-0.5
#define EPS 1e-6f

typedef unsigned long long u64;
typedef unsigned int u32;

// ---------------- scratch (static device memory, allowed) ----------------
__device__ float g_qkvz[S_LEN * QKVZ_DIM];      // 9.4 MB
__device__ float g_ba  [S_LEN * 64];
__device__ float g_conv[S_LEN * CONV_DIM];      // 5.2 MB
__device__ float g_Vbt [VAL_DIM * S_LEN];       // [n=h*128+d][t]  (v*beta transposed)
__device__ float g_S   [NK * S_LEN * S_LEN];    // [g][s][t]  4 group score mats (1 MB)
__device__ float g_attn[S_LEN * VAL_DIM];       // [s][h*128+d]  (normalized+gated)
__device__ float g_part[4 * S_LEN * HID];       // out_proj K-split partials

// ================= low-level helpers =================
__device__ __forceinline__ u32 smem_u32(const void* p) {
    u32 a;
    asm("{ .reg .u64 t; cvta.to.shared.u64 t, %1; cvt.u32.u64 %0, t; }" : "=r"(a) : "l"(p));
    return a;
}
__device__ __forceinline__ void sts128(u32 addr, uint4 v) {
    asm volatile("st.shared.v4.b32 [%0], {%1,%2,%3,%4};"
                 :: "r"(addr), "r"(v.x), "r"(v.y), "r"(v.z), "r"(v.w) : "memory");
}
__device__ __forceinline__ void ldsm4(u32* r, u32 addr) {
    asm volatile("ldmatrix.sync.aligned.m8n8.x4.shared.b16 {%0,%1,%2,%3}, [%4];"
                 : "=r"(r[0]), "=r"(r[1]), "=r"(r[2]), "=r"(r[3]) : "r"(addr));
}
__device__ __forceinline__ void ldsm2(u32* r, u32 addr) {
    asm volatile("ldmatrix.sync.aligned.m8n8.x2.shared.b16 {%0,%1}, [%2];"
                 : "=r"(r[0]), "=r"(r[1]) : "r"(addr));
}
__device__ __forceinline__ void mma_f16(float* c, const u32* a, const u32* b) {
    asm volatile("mma.sync.aligned.m16n8k16.row.col.f32.f16.f16.f32 "
                 "{%0,%1,%2,%3}, {%4,%5,%6,%7}, {%8,%9}, {%0,%1,%2,%3};"
                 : "+f"(c[0]), "+f"(c[1]), "+f"(c[2]), "+f"(c[3])
                 : "r"(a[0]), "r"(a[1]), "r"(a[2]), "r"(a[3]), "r"(b[0]), "r"(b[1]));
}

__device__ __forceinline__ u32 packh(__half a, __half b) {
    __half2 h = __halves2half2(a, b);
    return *(u32*)&h;
}
// fp32 -> fp16 hi + fp16 lo (2-way split), 2 values packed per u32
__device__ __forceinline__ void cvt2s(float a, float b, u32& hi, u32& lo) {
    __half ha = __float2half_rn(a), hb = __float2half_rn(b);
    float ra = a - __half2float(ha), rb = b - __half2float(hb);
    hi = packh(ha, hb);
    lo = packh(__float2half_rn(ra), __float2half_rn(rb));
}
__device__ __forceinline__ void cvt8s(float4 p0, float4 p1, uint4& hi, uint4& lo) {
    cvt2s(p0.x, p0.y, hi.x, lo.x);
    cvt2s(p0.z, p0.w, hi.y, lo.y);
    cvt2s(p1.x, p1.y, hi.z, lo.z);
    cvt2s(p1.z, p1.w, hi.w, lo.w);
}
// fp32 -> fp16 single (for B operand)
__device__ __forceinline__ uint4 cvt8h(float4 p0, float4 p1) {
    uint4 r;
    __half2 h0 = __floats2half2_rn(p0.x, p0.y);
    __half2 h1 = __floats2half2_rn(p0.z, p0.w);
    __half2 h2 = __floats2half2_rn(p1.x, p1.y);
    __half2 h3 = __floats2half2_rn(p1.z, p1.w);
    r.x = *(u32*)&h0; r.y = *(u32*)&h1; r.z = *(u32*)&h2; r.w = *(u32*)&h3;
    return r;
}

// ================= mma.sync fp16 2-pass GEMM: C = A * B^T =================
// A [M,K] fp32 row-major (lda), B [N,K] fp32 row-major (ldb), C fp32 row-major.
// Tile 128x128, K-chunk 32, double-buffered SMEM: Ahi/Alo (fp16 split) + B (fp16).
// C = Ahi*B + Alo*B   (rel err ~2^-12 per GEMM).
// z-dim: ksplit>1 -> K-split; else batch mode (A += z*zA, B += z*zB, C += z*zC).
// fuse_rms: per-row (128 cols = one head) RMSNorm + silu(z)-gate fused in epilogue.
// SMEM stage (24KB): Ahi @0, Alo @8192, B @16384. 2 stages = 48KB.
#define MMA_SMEM_TOTAL 49664    // 48KB stages + 512B epilogue scratch

__global__ void __launch_bounds__(256)
gemm_mma(const float* __restrict__ A, int lda, int zA,
         const float* __restrict__ B, int ldb, int zB,
         float* __restrict__ C, int ldc, int zC,
         int Ktot, int ksplit, int causal, float scale,
         int fuse_rms, const float* __restrict__ zgate, const float* __restrict__ norm_w)
{
    extern __shared__ char smem[];
    const u32 sb = smem_u32(smem);
    float* rowsq = (float*)(smem + 49152);   // [128] epilogue scratch
    const int tid = threadIdx.x;
    const int wid = tid >> 5, lane = tid & 31;
    const int bm = blockIdx.x * 128, bn = blockIdx.y * 128;
    const int z = blockIdx.z;

    int kLen = Ktot, k0 = 0;
    if (ksplit > 1) {
        kLen = Ktot / ksplit;
        k0 = z * kLen;
        C += (size_t)z * zC;
    } else {
        A += (size_t)z * zA;
        B += (size_t)z * zB;
        C += (size_t)z * zC;
    }
    const int niter = kLen / 32;

    // ---- global load mapping: thread -> (row 0..127, 16-float half) ----
    const int grow = tid >> 1;
    const int ghalf = tid & 1;
    const float* Ap = A + (size_t)(bm + grow) * lda + k0 + ghalf * 16;
    const float* Bp = B + (size_t)(bn + grow) * ldb + k0 + ghalf * 16;
    const int ssw = (grow >> 1) & 3;
    const u32 st0 = (u32)(grow * 64 + (((ghalf * 2 + 0) ^ ssw) * 16));
    const u32 st1 = (u32)(grow * 64 + (((ghalf * 2 + 1) ^ ssw) * 16));

    // ---- warp tile: 2(m) x 4(n), each 64x32 ----
    const int wm = wid & 1, wn = wid >> 1;
    const int arow = wm * 64 + (lane & 15);
    const u32 arow_b = (u32)(arow * 64);
    const int aswz = (arow >> 1) & 3;
    const int ahi = lane >> 4;
    const int brow = wn * 32 + (lane & 7);
    const u32 brow_b = (u32)(brow * 64);
    const int bswz = (brow >> 1) & 3;
    const int bhi = (lane >> 3) & 1;

    float acc[4][4][4];
#pragma unroll
    for (int i = 0; i < 4; i++)
#pragma unroll
        for (int j = 0; j < 4; j++)
#pragma unroll
            for (int q = 0; q < 4; q++) acc[i][j][q] = 0.f;

    float4 ra[4], rb[4];
#pragma unroll
    for (int j = 0; j < 4; j++) {
        ra[j] = *(const float4*)(Ap + j * 4);
        rb[j] = *(const float4*)(Bp + j * 4);
    }

    for (int it = 0; it < niter; it++) {
        const u32 stg = sb + (u32)((it & 1) * 24576);
        // convert + store current chunk (A hi/lo split, B single fp16)
        {
            uint4 hi, lo;
            cvt8s(ra[0], ra[1], hi, lo);
            sts128(stg + st0, hi);
            sts128(stg + 8192 + st0, lo);
            cvt8s(ra[2], ra[3], hi, lo);
            sts128(stg + st1, hi);
            sts128(stg + 8192 + st1, lo);
            sts128(stg + 16384 + st0, cvt8h(rb[0], rb[1]));
            sts128(stg + 16384 + st1, cvt8h(rb[2], rb[3]));
        }
        // prefetch next chunk into registers (overlaps with compute)
        if (it + 1 < niter) {
            const float* a = Ap + (it + 1) * 32;
            const float* b = Bp + (it + 1) * 32;
#pragma unroll
            for (int j = 0; j < 4; j++) {
                ra[j] = *(const float4*)(a + j * 4);
                rb[j] = *(const float4*)(b + j * 4);
            }
        }
        __syncthreads();

#pragma unroll
        for (int ks = 0; ks < 2; ks++) {
            u32 ah[4][4], al[4][4], bh[4][2];
            const u32 ac = (u32)((((ks * 2 + ahi) ^ aswz)) * 16);
            const u32 abase = stg + arow_b + ac;
#pragma unroll
            for (int mi = 0; mi < 4; mi++) ldsm4(ah[mi], abase + mi * 1024);
#pragma unroll
            for (int mi = 0; mi < 4; mi++) ldsm4(al[mi], abase + 8192 + mi * 1024);
            const u32 bc = (u32)((((ks * 2 + bhi) ^ bswz)) * 16);
            const u32 bbase = stg + 16384 + brow_b + bc;
#pragma unroll
            for (int nj = 0; nj < 4; nj++) ldsm2(bh[nj], bbase + nj * 512);
#pragma unroll
            for (int mi = 0; mi < 4; mi++)
#pragma unroll
                for (int nj = 0; nj < 4; nj++) {
                    mma_f16(acc[mi][nj], ah[mi], bh[nj]);
                    mma_f16(acc[mi][nj], al[mi], bh[nj]);
                }
        }
        __syncthreads();
    }

    // ---- epilogue ----
    const int lrow0 = wm * 64 + (lane >> 2);          // local row in 0..127
    const int lcol0 = wn * 32 + (lane & 3) * 2;       // local col in 0..127
    const int crow0 = bm + lrow0;
    const int ccol0 = bn + lcol0;

    if (fuse_rms) {
        // per-row (one head) RMSNorm + silu(z) gate.  head index = z*8 + blockIdx.y
        if (tid < 128) rowsq[tid] = 0.f;
        __syncthreads();
#pragma unroll
        for (int mi = 0; mi < 4; mi++) {
            float a0 = 0.f, a1 = 0.f;
#pragma unroll
            for (int nj = 0; nj < 4; nj++) {
                a0 += acc[mi][nj][0] * acc[mi][nj][0] + acc[mi][nj][1] * acc[mi][nj][1];
                a1 += acc[mi][nj][2] * acc[mi][nj][2] + acc[mi][nj][3] * acc[mi][nj][3];
            }
            atomicAdd(&rowsq[lrow0 + mi * 16], a0);
            atomicAdd(&rowsq[lrow0 + mi * 16 + 8], a1);
        }
        __syncthreads();
        const int gh = z * 8 + blockIdx.y;            // head 0..31
#pragma unroll
        for (int mi = 0; mi < 4; mi++) {
            const int lr = lrow0 + mi * 16;
            const float r0 = rsqrtf(rowsq[lr] * (1.f / 128.f) + EPS);
            const float r1 = rsqrtf(rowsq[lr + 8] * (1.f / 128.f) + EPS);
            const int s0 = bm + lr, s1 = s0 + 8;
#pragma unroll
            for (int nj = 0; nj < 4; nj++) {
                const int d = lcol0 + nj * 8;         // local dv 0..127
                const float w0 = __ldg(norm_w + d), w1 = __ldg(norm_w + d + 1);
                const size_t zbase = (size_t)CONV_DIM + gh * 128 + d;
                float2 z0 = *(const float2*)(zgate + (size_t)s0 * QKVZ_DIM + zbase);
                float2 z1 = *(const float2*)(zgate + (size_t)s1 * QKVZ_DIM + zbase);
                const float g00 = z0.x / (1.f + expf(-z0.x));
                const float g01 = z0.y / (1.f + expf(-z0.y));
                const float g10 = z1.x / (1.f + expf(-z1.x));
                const float g11 = z1.y / (1.f + expf(-z1.y));
                const int c = ccol0 + nj * 8;
                *(float2*)(C + (size_t)s0 * ldc + c) =
                    make_float2(acc[mi][nj][0] * r0 * w0 * g00, acc[mi][nj][1] * r0 * w1 * g01);
                *(float2*)(C + (size_t)s1 * ldc + c) =
                    make_float2(acc[mi][nj][2] * r1 * w0 * g10, acc[mi][nj][3] * r1 * w1 * g11);
            }
        }
        return;
    }

    // plain epilogue (scale + optional causal mask: zero where col > row)
#pragma unroll
    for (int mi = 0; mi < 4; mi++)
#pragma unroll
        for (int nj = 0; nj < 4; nj++) {
            const int r = crow0 + mi * 16;
            const int c = ccol0 + nj * 8;
            float v0 = acc[mi][nj][0] * scale;
            float v1 = acc[mi][nj][1] * scale;
            float v2 = acc[mi][nj][2] * scale;
            float v3 = acc[mi][nj][3] * scale;
            if (causal) {
                if (c     > r)     v0 = 0.f;
                if (c + 1 > r)     v1 = 0.f;
                if (c     > r + 8) v2 = 0.f;
                if (c + 1 > r + 8) v3 = 0.f;
            }
            *(float2*)(C + (size_t)r * ldc + c) = make_float2(v0, v1);
            *(float2*)(C + (size_t)(r + 8) * ldc + c) = make_float2(v2, v3);
        }
}

// ---------------- ba = hs @ w_ba^T  (N=64, tiny) ----------------
__global__ void ba_gemm(const float* __restrict__ hs, const float* __restrict__ w,
                        float* __restrict__ ba)
{
    const int s = blockIdx.x;
    const int t = threadIdx.x;
    const int n = t & 63, kc = t >> 6;
    const float4* a = (const float4*)(hs + (size_t)s * HID + kc * 512);
    const float4* b = (const float4*)(w + (size_t)n * HID + kc * 512);
    float acc = 0.f;
#pragma unroll 8
    for (int i = 0; i < 128; i++) {
        float4 x = a[i], y = b[i];
        acc += x.x * y.x + x.y * y.y + x.z * y.z + x.w * y.w;
    }
    __shared__ float red[256];
    red[t] = acc;
    __syncthreads();
    if (t < 64)
        ba[s * 64 + n] = red[n] + red[n + 64] + red[n + 128] + red[n + 192];
}

// ---------------- causal depthwise conv (K=4) + SiLU, sliding window --------
// Each thread owns one channel, walks 32 sequence positions. grid (20, 8).
__global__ void conv_silu(const float* __restrict__ qkvz, const float* __restrict__ cw,
                          float* __restrict__ out)
{
    const int c = blockIdx.x * 256 + threadIdx.x;   // 0..5119
    const int s0 = blockIdx.y * 32;
    const float4 w = ((const float4*)cw)[c];
    float x0 = 0.f, x1 = 0.f, x2 = 0.f;
    if (s0 >= 1) x2 = qkvz[(size_t)(s0 - 1) * QKVZ_DIM + c];
    if (s0 >= 2) x1 = qkvz[(size_t)(s0 - 2) * QKVZ_DIM + c];
    if (s0 >= 3) x0 = qkvz[(size_t)(s0 - 3) * QKVZ_DIM + c];
#pragma unroll 4
    for (int i = 0; i < 32; i++) {
        const int s = s0 + i;
        float x3 = qkvz[(size_t)s * QKVZ_DIM + c];
        float acc = w.x * x0 + w.y * x1 + w.z * x2 + w.w * x3;
        out[(size_t)s * CONV_DIM + c] = acc / (1.f + expf(-acc));
        x0 = x1; x1 = x2; x2 = x3;
    }
}

// ---------------- Vbt = (v * beta)^T : [n][t], tiled transpose ----------------
__global__ void prep_vbt(const float* __restrict__ conv, const float* __restrict__ ba,
                         const float* __restrict__ dt_bias, float* __restrict__ Vbt)
{
    __shared__ float tile[32][33];
    const int n0 = blockIdx.x * 32, t0 = blockIdx.y * 32;
    const int tx = threadIdx.x, ty = threadIdx.y;   // 32 x 8
#pragma unroll
    for (int j = 0; j < 4; j++) {
        const int t = t0 + ty + j * 8;
        const int n = n0 + tx;
        const int h = n >> 7;
        float b = ba[t * 64 + h] + dt_bias[h];
        float beta = 1.f / (1.f + expf(-b));
        tile[ty + j * 8][tx] = conv[(size_t)t * CONV_DIM + 2 * KEY_DIM + n] * beta;
    }
    __syncthreads();
#pragma unroll
    for (int j = 0; j < 4; j++) {
        const int n = n0 + ty + j * 8;
        const int t = t0 + tx;
        Vbt[(size_t)n * S_LEN + t] = tile[tx][ty + j * 8];
    }
}

// ---------------- K-split partial reduction ----------------
__global__ void reduce4(const float* __restrict__ p, float* __restrict__ out)
{
    const int i = blockIdx.x * 256 + threadIdx.x;
    out[i] = p[i] + p[i + S_LEN * HID] + p[i + 2 * S_LEN * HID] + p[i + 3 * S_LEN * HID];
}

// ---------------- launch ----------------
extern "C" void kernel_launch(void* const* d_in, const int* in_sizes, int n_in,
                              void* d_out, int out_size)
{
    const float* hs      = (const float*)d_in[0];  // [256,2048]
    const float* w_qkvz  = (const float*)d_in[1];  // [9216,2048]
    const float* w_ba    = (const float*)d_in[2];  // [64,2048]
    const float* w_out   = (const float*)d_in[3];  // [2048,4096]
    const float* conv_w  = (const float*)d_in[4];  // [5120,1,4]
    const float* dt_bias = (const float*)d_in[5];  // [32]
    const float* norm_w  = (const float*)d_in[7];  // [128]
    float* out = (float*)d_out;

    float *qkvz, *ba, *conv, *Vbt, *Sb, *attn, *part;
    cudaGetSymbolAddress((void**)&qkvz, g_qkvz);
    cudaGetSymbolAddress((void**)&ba,   g_ba);
    cudaGetSymbolAddress((void**)&conv, g_conv);
    cudaGetSymbolAddress((void**)&Vbt,  g_Vbt);
    cudaGetSymbolAddress((void**)&Sb,   g_S);
    cudaGetSymbolAddress((void**)&attn, g_attn);
    cudaGetSymbolAddress((void**)&part, g_part);

    static int smem_set = 0;
    if (!smem_set) {
        cudaFuncSetAttribute(gemm_mma, cudaFuncAttributeMaxDynamicSharedMemorySize,
                             MMA_SMEM_TOTAL);
        smem_set = 1;
    }

    // 1) qkvz = hs @ w_qkvz^T : [256,9216]
    gemm_mma<<<dim3(2, 72, 1), 256, MMA_SMEM_TOTAL>>>(
        hs, HID, 0, w_qkvz, HID, 0, qkvz, QKVZ_DIM, 0, HID, 1, 0, 1.f,
        0, nullptr, nullptr);
    // 2) ba = hs @ w_ba^T : [256,64]
    ba_gemm<<<256, 256>>>(hs, w_ba, ba);
    // 3) causal depthwise conv + silu (first 5120 cols of qkvz)
    conv_silu<<<dim3(20, 8), 256>>>(qkvz, conv_w, conv);
    // 4) Vbt transpose with beta gating
    prep_vbt<<<dim3(VAL_DIM / 32, S_LEN / 32), dim3(32, 8)>>>(conv, ba, dt_bias, Vbt);
    // 5) S_g = Q_SCALE * tril(q_g k_g^T) : 4 groups x [256,256], direct from conv
    gemm_mma<<<dim3(2, 2, NK), 256, MMA_SMEM_TOTAL>>>(
        conv, CONV_DIM, DK, conv + KEY_DIM, CONV_DIM, DK,
        Sb, S_LEN, S_LEN * S_LEN, DK, 1, 1, Q_SCALE,
        0, nullptr, nullptr);
    // 6) O = S_g @ Vbt_g^T with FUSED gated RMSNorm -> attn [s][h*128+d]
    gemm_mma<<<dim3(2, 8, NK), 256, MMA_SMEM_TOTAL>>>(
        Sb, S_LEN, S_LEN * S_LEN, Vbt, S_LEN, 1024 * S_LEN,
        attn, VAL_DIM, 1024, S_LEN, 1, 0, 1.f,
        1, qkvz, norm_w);
    // 7) out_proj (K-split 4) -> partials
    gemm_mma<<<dim3(2, 16, 4), 256, MMA_SMEM_TOTAL>>>(
        attn, VAL_DIM, 0, w_out, VAL_DIM, 0, part, HID, S_LEN * HID,
        VAL_DIM, 4, 0, 1.f,
        0, nullptr, nullptr);
    // 8) reduce partials -> d_out
    reduce4<<<S_LEN * HID / 256, 256>>>(part, out);
}

// round 10
// speedup vs baseline: 1.3097x; 1.0847x over previous
#include <cuda_runtime.h>
#include <cuda_bf16.h>
#include <cuda_fp16.h>
#include <cstdint>

// ---------------- problem constants ----------------
#define S_LEN   256
#define HID     2048
#define NK      4
#define NV      32
#define DK      128
#define DV      128
#define KEY_DIM 512          // NK*DK
#define VAL_DIM 4096         // NV*DV
#define CONV_DIM 5120        // 2*KEY_DIM + VAL_DIM
#define QKVZ_DIM 9216        // 2*KEY_DIM + 2*VAL_DIM
#define Q_SCALE 0.08838834764831845f   // DK^-0.5
#define EPS 1e-6f

typedef unsigned long long u64;
typedef unsigned int u32;

// ---------------- scratch (static device memory, allowed) ----------------
__device__ float  g_qkvz[S_LEN * QKVZ_DIM];     // fp32 (z gate read from here)
__device__ __half g_hsh[S_LEN * HID];           // hs hi
__device__ __half g_hsl[S_LEN * HID];           // hs lo
__device__ float  g_bapart[16 * S_LEN * 64];    // ba K-split partials
__device__ float  g_ba[S_LEN * 64];
__device__ __half g_qh[S_LEN * KEY_DIM];        // conv-silu q hi
__device__ __half g_ql[S_LEN * KEY_DIM];        // conv-silu q lo
__device__ __half g_kh[S_LEN * KEY_DIM];        // conv-silu k (fp16)
__device__ float  g_convv[S_LEN * VAL_DIM];     // conv-silu v (fp32)
__device__ __half g_vbth[VAL_DIM * S_LEN];      // (v*beta)^T fp16
__device__ __half g_Sh[NK * S_LEN * S_LEN];     // scores hi
__device__ __half g_Sl[NK * S_LEN * S_LEN];     // scores lo
__device__ __half g_attnh[S_LEN * VAL_DIM];     // gated attn hi
__device__ __half g_attnl[S_LEN * VAL_DIM];     // gated attn lo
__device__ float  g_part[4 * S_LEN * HID];      // out_proj K-split partials

// ================= low-level helpers =================
__device__ __forceinline__ u32 smem_u32(const void* p) {
    u32 a;
    asm("{ .reg .u64 t; cvta.to.shared.u64 t, %1; cvt.u32.u64 %0, t; }" : "=r"(a) : "l"(p));
    return a;
}
__device__ __forceinline__ void sts128(u32 addr, uint4 v) {
    asm volatile("st.shared.v4.b32 [%0], {%1,%2,%3,%4};"
                 :: "r"(addr), "r"(v.x), "r"(v.y), "r"(v.z), "r"(v.w) : "memory");
}
__device__ __forceinline__ void ldsm4(u32* r, u32 addr) {
    asm volatile("ldmatrix.sync.aligned.m8n8.x4.shared.b16 {%0,%1,%2,%3}, [%4];"
                 : "=r"(r[0]), "=r"(r[1]), "=r"(r[2]), "=r"(r[3]) : "r"(addr));
}
__device__ __forceinline__ void ldsm2(u32* r, u32 addr) {
    asm volatile("ldmatrix.sync.aligned.m8n8.x2.shared.b16 {%0,%1}, [%2];"
                 : "=r"(r[0]), "=r"(r[1]) : "r"(addr));
}
__device__ __forceinline__ void mma_f16(float* c, const u32* a, const u32* b) {
    asm volatile("mma.sync.aligned.m16n8k16.row.col.f32.f16.f16.f32 "
                 "{%0,%1,%2,%3}, {%4,%5,%6,%7}, {%8,%9}, {%0,%1,%2,%3};"
                 : "+f"(c[0]), "+f"(c[1]), "+f"(c[2]), "+f"(c[3])
                 : "r"(a[0]), "r"(a[1]), "r"(a[2]), "r"(a[3]), "r"(b[0]), "r"(b[1]));
}

__device__ __forceinline__ u32 packh(__half a, __half b) {
    __half2 h = __halves2half2(a, b);
    return *(u32*)&h;
}
// fp32 pair -> fp16 hi pair + fp16 lo pair (packed u32)
__device__ __forceinline__ void cvt2s(float a, float b, u32& hi, u32& lo) {
    __half ha = __float2half_rn(a), hb = __float2half_rn(b);
    float ra = a - __half2float(ha), rb = b - __half2float(hb);
    hi = packh(ha, hb);
    lo = packh(__float2half_rn(ra), __float2half_rn(rb));
}
// fp32 x8 -> fp16 single (B operand, weights)
__device__ __forceinline__ uint4 cvt8h(float4 p0, float4 p1) {
    uint4 r;
    __half2 h0 = __floats2half2_rn(p0.x, p0.y);
    __half2 h1 = __floats2half2_rn(p0.z, p0.w);
    __half2 h2 = __floats2half2_rn(p1.x, p1.y);
    __half2 h3 = __floats2half2_rn(p1.z, p1.w);
    r.x = *(u32*)&h0; r.y = *(u32*)&h1; r.z = *(u32*)&h2; r.w = *(u32*)&h3;
    return r;
}

// ================= mma.sync fp16 2-pass GEMM: C = A * B^T =================
// A pre-split to fp16 hi/lo (Ah/Al, [M,K] row-major, lda in elems).
// BMODE 0: B fp32 [N,K] (in-loop cvt to fp16);  BMODE 1: B fp16 [N,K].
// emode 0: fp32 C, *scale.  emode 1: causal+scale, split fp16 out (Ch/Cl).
// emode 2: fused per-head RMSNorm + silu(zgate) gate, split fp16 out.
// z-dim: ksplit>1 -> K-split into C + z*zC; else batch (A/B/C advance by zA/zB/zC).
#define MMA_SMEM_TOTAL 49664    // 48KB stages + 512B epilogue scratch

template<int BMODE>
__global__ void __launch_bounds__(256)
gemm_mma(const __half* __restrict__ Ah, const __half* __restrict__ Al, int lda, int zA,
         const void* __restrict__ Bv, int ldb, int zB,
         float* __restrict__ C, __half* __restrict__ Ch, __half* __restrict__ Cl,
         int ldc, int zC,
         int Ktot, int ksplit, float scale, int emode,
         const float* __restrict__ zgate, const float* __restrict__ norm_w)
{
    extern __shared__ char smem[];
    const u32 sb = smem_u32(smem);
    float* rowsq = (float*)(smem + 49152);   // [128] epilogue scratch
    const int tid = threadIdx.x;
    const int wid = tid >> 5, lane = tid & 31;
    const int bm = blockIdx.x * 128, bn = blockIdx.y * 128;
    const int z = blockIdx.z;

    int kLen = Ktot, k0 = 0;
    if (ksplit > 1) {
        kLen = Ktot / ksplit;
        k0 = z * kLen;
        C += (size_t)z * zC;
    } else {
        Ah += (size_t)z * zA;
        Al += (size_t)z * zA;
        Bv = (const void*)((const char*)Bv + (size_t)z * zB * (BMODE ? 2 : 4));
        C += (size_t)z * zC;
        Ch += (size_t)z * zC;
        Cl += (size_t)z * zC;
    }
    const int niter = kLen / 32;

    // ---- global load mapping: thread -> (row 0..127, 16-elem half of K32) ----
    const int grow = tid >> 1;
    const int ghalf = tid & 1;
    const __half* Aph = Ah + (size_t)(bm + grow) * lda + k0 + ghalf * 16;
    const __half* Apl = Al + (size_t)(bm + grow) * lda + k0 + ghalf * 16;
    const int ssw = (grow >> 1) & 3;
    const u32 st0 = (u32)(grow * 64 + (((ghalf * 2 + 0) ^ ssw) * 16));
    const u32 st1 = (u32)(grow * 64 + (((ghalf * 2 + 1) ^ ssw) * 16));

    // ---- warp tile: 2(m) x 4(n), each 64x32 ----
    const int wm = wid & 1, wn = wid >> 1;
    const int arow = wm * 64 + (lane & 15);
    const u32 arow_b = (u32)(arow * 64);
    const int aswz = (arow >> 1) & 3;
    const int ahi = lane >> 4;
    const int brow = wn * 32 + (lane & 7);
    const u32 brow_b = (u32)(brow * 64);
    const int bswz = (brow >> 1) & 3;
    const int bhi = (lane >> 3) & 1;

    float acc[4][4][4];
#pragma unroll
    for (int i = 0; i < 4; i++)
#pragma unroll
        for (int j = 0; j < 4; j++)
#pragma unroll
            for (int q = 0; q < 4; q++) acc[i][j][q] = 0.f;

    // prefetch registers
    uint4 rh0, rh1, rl0, rl1;
    uint4 rbh0, rbh1;           // BMODE 1
    float4 rbf[4];              // BMODE 0
    const __half*  Bph = (const __half*)Bv;
    const float*   Bpf = (const float*)Bv;
    if (BMODE) {
        Bph += (size_t)(bn + grow) * ldb + k0 + ghalf * 16;
    } else {
        Bpf += (size_t)(bn + grow) * ldb + k0 + ghalf * 16;
    }

    // load chunk 0
    rh0 = *(const uint4*)(Aph);
    rh1 = *(const uint4*)(Aph + 8);
    rl0 = *(const uint4*)(Apl);
    rl1 = *(const uint4*)(Apl + 8);
    if (BMODE) {
        rbh0 = *(const uint4*)(Bph);
        rbh1 = *(const uint4*)(Bph + 8);
    } else {
#pragma unroll
        for (int j = 0; j < 4; j++) rbf[j] = *(const float4*)(Bpf + j * 4);
    }

    for (int it = 0; it < niter; it++) {
        const u32 stg = sb + (u32)((it & 1) * 24576);
        // store current chunk
        sts128(stg + st0, rh0);
        sts128(stg + st1, rh1);
        sts128(stg + 8192 + st0, rl0);
        sts128(stg + 8192 + st1, rl1);
        if (BMODE) {
            sts128(stg + 16384 + st0, rbh0);
            sts128(stg + 16384 + st1, rbh1);
        } else {
            sts128(stg + 16384 + st0, cvt8h(rbf[0], rbf[1]));
            sts128(stg + 16384 + st1, cvt8h(rbf[2], rbf[3]));
        }
        // prefetch next chunk
        if (it + 1 < niter) {
            const int off = (it + 1) * 32;
            rh0 = *(const uint4*)(Aph + off);
            rh1 = *(const uint4*)(Aph + off + 8);
            rl0 = *(const uint4*)(Apl + off);
            rl1 = *(const uint4*)(Apl + off + 8);
            if (BMODE) {
                rbh0 = *(const uint4*)(Bph + off);
                rbh1 = *(const uint4*)(Bph + off + 8);
            } else {
#pragma unroll
                for (int j = 0; j < 4; j++) rbf[j] = *(const float4*)(Bpf + off + j * 4);
            }
        }
        __syncthreads();

#pragma unroll
        for (int ks = 0; ks < 2; ks++) {
            u32 ah[4][4], al[4][4], bh[4][2];
            const u32 ac = (u32)((((ks * 2 + ahi) ^ aswz)) * 16);
            const u32 abase = stg + arow_b + ac;
#pragma unroll
            for (int mi = 0; mi < 4; mi++) ldsm4(ah[mi], abase + mi * 1024);
#pragma unroll
            for (int mi = 0; mi < 4; mi++) ldsm4(al[mi], abase + 8192 + mi * 1024);
            const u32 bc = (u32)((((ks * 2 + bhi) ^ bswz)) * 16);
            const u32 bbase = stg + 16384 + brow_b + bc;
#pragma unroll
            for (int nj = 0; nj < 4; nj++) ldsm2(bh[nj], bbase + nj * 512);
#pragma unroll
            for (int mi = 0; mi < 4; mi++)
#pragma unroll
                for (int nj = 0; nj < 4; nj++) {
                    mma_f16(acc[mi][nj], ah[mi], bh[nj]);
                    mma_f16(acc[mi][nj], al[mi], bh[nj]);
                }
        }
        __syncthreads();
    }

    // ---- epilogue ----
    const int lrow0 = wm * 64 + (lane >> 2);          // local row 0..127
    const int lcol0 = wn * 32 + (lane & 3) * 2;       // local col 0..127
    const int crow0 = bm + lrow0;
    const int ccol0 = bn + lcol0;

    if (emode == 2) {
        // per-row (one head) RMSNorm + silu(z) gate, split fp16 out
        if (tid < 128) rowsq[tid] = 0.f;
        __syncthreads();
#pragma unroll
        for (int mi = 0; mi < 4; mi++) {
            float a0 = 0.f, a1 = 0.f;
#pragma unroll
            for (int nj = 0; nj < 4; nj++) {
                a0 += acc[mi][nj][0] * acc[mi][nj][0] + acc[mi][nj][1] * acc[mi][nj][1];
                a1 += acc[mi][nj][2] * acc[mi][nj][2] + acc[mi][nj][3] * acc[mi][nj][3];
            }
            atomicAdd(&rowsq[lrow0 + mi * 16], a0);
            atomicAdd(&rowsq[lrow0 + mi * 16 + 8], a1);
        }
        __syncthreads();
        const int gh = z * 8 + blockIdx.y;            // head 0..31
#pragma unroll
        for (int mi = 0; mi < 4; mi++) {
            const int lr = lrow0 + mi * 16;
            const float r0 = rsqrtf(rowsq[lr] * (1.f / 128.f) + EPS);
            const float r1 = rsqrtf(rowsq[lr + 8] * (1.f / 128.f) + EPS);
            const int s0 = bm + lr, s1 = s0 + 8;
#pragma unroll
            for (int nj = 0; nj < 4; nj++) {
                const int d = lcol0 + nj * 8;
                const float w0 = __ldg(norm_w + d), w1 = __ldg(norm_w + d + 1);
                const size_t zbase = (size_t)CONV_DIM + gh * 128 + d;
                float2 z0 = *(const float2*)(zgate + (size_t)s0 * QKVZ_DIM + zbase);
                float2 z1 = *(const float2*)(zgate + (size_t)s1 * QKVZ_DIM + zbase);
                const float g00 = z0.x / (1.f + expf(-z0.x));
                const float g01 = z0.y / (1.f + expf(-z0.y));
                const float g10 = z1.x / (1.f + expf(-z1.x));
                const float g11 = z1.y / (1.f + expf(-z1.y));
                const int c = ccol0 + nj * 8;
                u32 hi, lo;
                cvt2s(acc[mi][nj][0] * r0 * w0 * g00, acc[mi][nj][1] * r0 * w1 * g01, hi, lo);
                *(u32*)(Ch + (size_t)s0 * ldc + c) = hi;
                *(u32*)(Cl + (size_t)s0 * ldc + c) = lo;
                cvt2s(acc[mi][nj][2] * r1 * w0 * g10, acc[mi][nj][3] * r1 * w1 * g11, hi, lo);
                *(u32*)(Ch + (size_t)s1 * ldc + c) = hi;
                *(u32*)(Cl + (size_t)s1 * ldc + c) = lo;
            }
        }
        return;
    }

    if (emode == 1) {
        // causal mask + scale, split fp16 out
#pragma unroll
        for (int mi = 0; mi < 4; mi++)
#pragma unroll
            for (int nj = 0; nj < 4; nj++) {
                const int r = crow0 + mi * 16;
                const int c = ccol0 + nj * 8;
                float v0 = acc[mi][nj][0] * scale;
                float v1 = acc[mi][nj][1] * scale;
                float v2 = acc[mi][nj][2] * scale;
                float v3 = acc[mi][nj][3] * scale;
                if (c     > r)     v0 = 0.f;
                if (c + 1 > r)     v1 = 0.f;
                if (c     > r + 8) v2 = 0.f;
                if (c + 1 > r + 8) v3 = 0.f;
                u32 hi, lo;
                cvt2s(v0, v1, hi, lo);
                *(u32*)(Ch + (size_t)r * ldc + c) = hi;
                *(u32*)(Cl + (size_t)r * ldc + c) = lo;
                cvt2s(v2, v3, hi, lo);
                *(u32*)(Ch + (size_t)(r + 8) * ldc + c) = hi;
                *(u32*)(Cl + (size_t)(r + 8) * ldc + c) = lo;
            }
        return;
    }

    // plain fp32 epilogue
#pragma unroll
    for (int mi = 0; mi < 4; mi++)
#pragma unroll
        for (int nj = 0; nj < 4; nj++) {
            const int r = crow0 + mi * 16;
            const int c = ccol0 + nj * 8;
            *(float2*)(C + (size_t)r * ldc + c) =
                make_float2(acc[mi][nj][0] * scale, acc[mi][nj][1] * scale);
            *(float2*)(C + (size_t)(r + 8) * ldc + c) =
                make_float2(acc[mi][nj][2] * scale, acc[mi][nj][3] * scale);
        }
}

// ---------------- hs -> fp16 hi/lo split ----------------
__global__ void hs_split(const float* __restrict__ hs,
                         __half* __restrict__ hh, __half* __restrict__ hl)
{
    const int i = blockIdx.x * 256 + threadIdx.x;
    float x = hs[i];
    __half hi = __float2half_rn(x);
    hh[i] = hi;
    hl[i] = __float2half_rn(x - __half2float(hi));
}

// ---------------- ba: smem-tiled K-split GEMM + reduce ----------------
// grid (16,16): x = K-chunk of 128, y = 16-s group. part[16][256][64].
__global__ void ba_gemm2(const float* __restrict__ hs, const float* __restrict__ w,
                         float* __restrict__ part)
{
    __shared__ float ws[64][129];
    __shared__ float hss[16][129];
    const int tid = threadIdx.x;
    const int kc = blockIdx.x, sg = blockIdx.y;
    for (int i = tid; i < 64 * 128; i += 256) {
        const int n = i >> 7, k = i & 127;
        ws[n][k] = w[n * HID + kc * 128 + k];
    }
    for (int i = tid; i < 16 * 128; i += 256) {
        const int s = i >> 7, k = i & 127;
        hss[s][k] = hs[(size_t)(sg * 16 + s) * HID + kc * 128 + k];
    }
    __syncthreads();
    const int n = tid & 63, si = (tid >> 6) * 4;
    float a0 = 0.f, a1 = 0.f, a2 = 0.f, a3 = 0.f;
#pragma unroll 8
    for (int k = 0; k < 128; k++) {
        const float wv = ws[n][k];
        a0 += hss[si + 0][k] * wv;
        a1 += hss[si + 1][k] * wv;
        a2 += hss[si + 2][k] * wv;
        a3 += hss[si + 3][k] * wv;
    }
    float* p = part + kc * (S_LEN * 64) + (sg * 16 + si) * 64 + n;
    p[0] = a0; p[64] = a1; p[128] = a2; p[192] = a3;
}
__global__ void ba_reduce(const float* __restrict__ part, float* __restrict__ ba)
{
    const int i = blockIdx.x * 256 + threadIdx.x;    // 16384 outputs
    float s = 0.f;
#pragma unroll
    for (int kc = 0; kc < 16; kc++) s += part[kc * (S_LEN * 64) + i];
    ba[i] = s;
}

// ---------------- causal depthwise conv (K=4) + SiLU -> fp16 q/k, fp32 v ----
__global__ void conv_silu(const float* __restrict__ qkvz, const float* __restrict__ cw,
                          __half* __restrict__ qh, __half* __restrict__ ql,
                          __half* __restrict__ kh, float* __restrict__ vv)
{
    const int c = blockIdx.x * 256 + threadIdx.x;   // 0..5119
    const int s0 = blockIdx.y * 32;
    const float4 w = ((const float4*)cw)[c];
    float x0 = 0.f, x1 = 0.f, x2 = 0.f;
    if (s0 >= 1) x2 = qkvz[(size_t)(s0 - 1) * QKVZ_DIM + c];
    if (s0 >= 2) x1 = qkvz[(size_t)(s0 - 2) * QKVZ_DIM + c];
    if (s0 >= 3) x0 = qkvz[(size_t)(s0 - 3) * QKVZ_DIM + c];
#pragma unroll 4
    for (int i = 0; i < 32; i++) {
        const int s = s0 + i;
        float x3 = qkvz[(size_t)s * QKVZ_DIM + c];
        float acc = w.x * x0 + w.y * x1 + w.z * x2 + w.w * x3;
        float y = acc / (1.f + expf(-acc));
        if (c < KEY_DIM) {
            __half hi = __float2half_rn(y);
            qh[(size_t)s * KEY_DIM + c] = hi;
            ql[(size_t)s * KEY_DIM + c] = __float2half_rn(y - __half2float(hi));
        } else if (c < 2 * KEY_DIM) {
            kh[(size_t)s * KEY_DIM + (c - KEY_DIM)] = __float2half_rn(y);
        } else {
            vv[(size_t)s * VAL_DIM + (c - 2 * KEY_DIM)] = y;
        }
        x0 = x1; x1 = x2; x2 = x3;
    }
}

// ---------------- Vbt = (v * beta)^T fp16 : [n][t] ----------------
__global__ void prep_vbt(const float* __restrict__ vv, const float* __restrict__ ba,
                         const float* __restrict__ dt_bias, __half* __restrict__ Vbt)
{
    __shared__ float tile[32][33];
    const int n0 = blockIdx.x * 32, t0 = blockIdx.y * 32;
    const int tx = threadIdx.x, ty = threadIdx.y;   // 32 x 8
#pragma unroll
    for (int j = 0; j < 4; j++) {
        const int t = t0 + ty + j * 8;
        const int n = n0 + tx;
        const int h = n >> 7;
        float b = ba[t * 64 + h] + dt_bias[h];
        float beta = 1.f / (1.f + expf(-b));
        tile[ty + j * 8][tx] = vv[(size_t)t * VAL_DIM + n] * beta;
    }
    __syncthreads();
#pragma unroll
    for (int j = 0; j < 4; j++) {
        const int n = n0 + ty + j * 8;
        const int t = t0 + tx;
        Vbt[(size_t)n * S_LEN + t] = __float2half_rn(tile[tx][ty + j * 8]);
    }
}

// ---------------- K-split partial reduction ----------------
__global__ void reduce4(const float* __restrict__ p, float* __restrict__ out)
{
    const int i = blockIdx.x * 256 + threadIdx.x;
    out[i] = p[i] + p[i + S_LEN * HID] + p[i + 2 * S_LEN * HID] + p[i + 3 * S_LEN * HID];
}

// ---------------- launch ----------------
extern "C" void kernel_launch(void* const* d_in, const int* in_sizes, int n_in,
                              void* d_out, int out_size)
{
    const float* hs      = (const float*)d_in[0];  // [256,2048]
    const float* w_qkvz  = (const float*)d_in[1];  // [9216,2048]
    const float* w_ba    = (const float*)d_in[2];  // [64,2048]
    const float* w_out   = (const float*)d_in[3];  // [2048,4096]
    const float* conv_w  = (const float*)d_in[4];  // [5120,1,4]
    const float* dt_bias = (const float*)d_in[5];  // [32]
    const float* norm_w  = (const float*)d_in[7];  // [128]
    float* out = (float*)d_out;

    float *qkvz, *ba, *bapart, *convv, *part;
    __half *hsh, *hsl, *qh, *ql, *kh, *vbth, *Sh, *Sl, *attnh, *attnl;
    cudaGetSymbolAddress((void**)&qkvz,   g_qkvz);
    cudaGetSymbolAddress((void**)&hsh,    g_hsh);
    cudaGetSymbolAddress((void**)&hsl,    g_hsl);
    cudaGetSymbolAddress((void**)&bapart, g_bapart);
    cudaGetSymbolAddress((void**)&ba,     g_ba);
    cudaGetSymbolAddress((void**)&qh,     g_qh);
    cudaGetSymbolAddress((void**)&ql,     g_ql);
    cudaGetSymbolAddress((void**)&kh,     g_kh);
    cudaGetSymbolAddress((void**)&convv,  g_convv);
    cudaGetSymbolAddress((void**)&vbth,   g_vbth);
    cudaGetSymbolAddress((void**)&Sh,     g_Sh);
    cudaGetSymbolAddress((void**)&Sl,     g_Sl);
    cudaGetSymbolAddress((void**)&attnh,  g_attnh);
    cudaGetSymbolAddress((void**)&attnl,  g_attnl);
    cudaGetSymbolAddress((void**)&part,   g_part);

    static int smem_set = 0;
    if (!smem_set) {
        cudaFuncSetAttribute(gemm_mma<0>, cudaFuncAttributeMaxDynamicSharedMemorySize,
                             MMA_SMEM_TOTAL);
        cudaFuncSetAttribute(gemm_mma<1>, cudaFuncAttributeMaxDynamicSharedMemorySize,
                             MMA_SMEM_TOTAL);
        smem_set = 1;
    }

    // 0) hs -> fp16 hi/lo
    hs_split<<<S_LEN * HID / 256, 256>>>(hs, hsh, hsl);
    // 1) qkvz = hs @ w_qkvz^T : [256,9216]  (B = fp32 weights)
    gemm_mma<0><<<dim3(2, 72, 1), 256, MMA_SMEM_TOTAL>>>(
        hsh, hsl, HID, 0, w_qkvz, HID, 0,
        qkvz, nullptr, nullptr, QKVZ_DIM, 0, HID, 1, 1.f, 0, nullptr, nullptr);
    // 2) ba = hs @ w_ba^T (smem-tiled K-split)
    ba_gemm2<<<dim3(16, 16), 256>>>(hs, w_ba, bapart);
    ba_reduce<<<S_LEN * 64 / 256, 256>>>(bapart, ba);
    // 3) conv + silu -> q hi/lo fp16, k fp16, v fp32
    conv_silu<<<dim3(20, 8), 256>>>(qkvz, conv_w, qh, ql, kh, convv);
    // 4) Vbt fp16 transpose with beta gating
    prep_vbt<<<dim3(VAL_DIM / 32, S_LEN / 32), dim3(32, 8)>>>(convv, ba, dt_bias, vbth);
    // 5) S_g = Q_SCALE * tril(q_g k_g^T), split fp16 out : 4 x [256,256]
    gemm_mma<1><<<dim3(2, 2, NK), 256, MMA_SMEM_TOTAL>>>(
        qh, ql, KEY_DIM, DK, kh, KEY_DIM, DK,
        nullptr, Sh, Sl, S_LEN, S_LEN * S_LEN, DK, 1, Q_SCALE, 1, nullptr, nullptr);
    // 6) O = S_g @ Vbt_g^T, fused gated RMSNorm, split fp16 out -> attn
    gemm_mma<1><<<dim3(2, 8, NK), 256, MMA_SMEM_TOTAL>>>(
        Sh, Sl, S_LEN, S_LEN * S_LEN, vbth, S_LEN, 1024 * S_LEN,
        nullptr, attnh, attnl, VAL_DIM, 1024, S_LEN, 1, 1.f, 2, qkvz, norm_w);
    // 7) out_proj (K-split 4) -> partials  (B = fp32 weights)
    gemm_mma<0><<<dim3(2, 16, 4), 256, MMA_SMEM_TOTAL>>>(
        attnh, attnl, VAL_DIM, 0, w_out, VAL_DIM, 0,
        part, nullptr, nullptr, HID, S_LEN * HID, VAL_DIM, 4, 1.f, 0, nullptr, nullptr);
    // 8) reduce partials -> d_out
    reduce4<<<S_LEN * HID / 256, 256>>>(part, out);
}